// round 8
// baseline (speedup 1.0000x reference)
#include <cuda_runtime.h>
#include <cuda_bf16.h>

#define NN 50000
#define EE 800000
#define F_INN 256
#define F_EDGE 64
#define NH 4
#define ND 64
#define HD 256
#define NEG_SLOPE 0.2f
#define NBLK 196   // ceil(NN/256)

// ---------------- scratch (static device globals; no allocation) ----------------
__device__ __nv_bfloat162 g_featb[NN * 128]; // h @ W_fc^T in bf16 pairs
__device__ float g_res[NN * HD];             // h @ W_res^T
__device__ float g_e[EE * NH];               // leaky-relu logits
__device__ float g_el[NN * NH];
__device__ float g_er[NN * NH];
__device__ float g_V[F_EDGE * NH];           // collapsed W_edge x attn_e, layout [j][h]
__device__ int   g_cnt[NN];                  // in-degree
__device__ int   g_off[NN];                  // CSR offsets (exclusive scan of cnt)
__device__ int   g_cur[NN];                  // scatter cursors
__device__ int   g_bsum[256];                // block sums for scan
__device__ int   g_bpre[256];                // block prefix
__device__ int   g_eidx[EE];                 // CSR: edge id per slot

// ---------------- helpers ----------------
__device__ __forceinline__ unsigned f2tf32(float f) {
    unsigned u;
    asm("cvt.rna.tf32.f32 %0, %1;" : "=r"(u) : "f"(f));
    return u;
}

__device__ __forceinline__ void mma_tf32(float& c0, float& c1, float& c2, float& c3,
                                         unsigned a0, unsigned a1, unsigned a2, unsigned a3,
                                         unsigned b0, unsigned b1) {
    asm volatile("mma.sync.aligned.m16n8k8.row.col.f32.tf32.tf32.f32 "
                 "{%0,%1,%2,%3}, {%4,%5,%6,%7}, {%8,%9}, {%0,%1,%2,%3};"
                 : "+f"(c0), "+f"(c1), "+f"(c2), "+f"(c3)
                 : "r"(a0), "r"(a1), "r"(a2), "r"(a3), "r"(b0), "r"(b1));
}

__device__ __forceinline__ void cp16(float* smem, const float* gmem) {
    unsigned s = (unsigned)__cvta_generic_to_shared(smem);
    asm volatile("cp.async.cg.shared.global [%0], [%1], 16;" :: "r"(s), "l"(gmem));
}

// ---------------- K0: init scratch (small arrays only) ----------------
__global__ void k_init() {
    int i = blockIdx.x * blockDim.x + threadIdx.x;
    if (i < NN) { g_cnt[i] = 0; g_cur[i] = 0; }
}

// ---------------- K1: collapse W_edge with attn_e -> V [64,4] ----------------
__global__ void k_prep(const float* __restrict__ W_edge, const float* __restrict__ attn_e) {
    int tid = threadIdx.x;             // 256 threads
    int j = tid & 63, h = tid >> 6;
    float s = 0.0f;
    #pragma unroll 8
    for (int d = 0; d < 64; d++)
        s += W_edge[(h * 64 + d) * 64 + j] * attn_e[h * 64 + d];
    g_V[j * 4 + h] = s;
}

// ---------------- K2: tf32 GEMM with cp.async 2-stage, in-place cvt ----------
#define GBM 128
#define GBN 128
#define GBK 16
#define KT  (F_INN / GBK)   // 16
#define SPAD 20             // words per row; conflict-free frag loads

__global__ __launch_bounds__(256) void k_gemm_tc(const float* __restrict__ A,
                                                 const float* __restrict__ Wfc,
                                                 const float* __restrict__ Wres) {
    __shared__ float As[2][GBM * SPAD];
    __shared__ float Bs[2][GBN * SPAD];

    const int colbase = blockIdx.x * GBN;    // 0,128,256,384
    const int rowbase = blockIdx.y * GBM;
    const bool isfeat = (colbase < 256);
    const float* Bsrc = isfeat ? (Wfc + colbase * F_INN)
                               : (Wres + (colbase - 256) * F_INN);
    const int ccol0 = isfeat ? colbase : colbase - 256;

    const int tid  = threadIdx.x;
    const int w    = tid >> 5;
    const int lane = tid & 31;
    const int grp  = lane >> 2;     // 0..7
    const int tg   = lane & 3;      // 0..3
    const int wm   = w & 1;
    const int wn   = w >> 1;

    const int lr  = tid >> 2;          // 0..63 (+64 on second pass)
    const int lc4 = (tid & 3) * 4;     // 0,4,8,12

    float acc[4][4][4];
    #pragma unroll
    for (int mt = 0; mt < 4; mt++)
        #pragma unroll
        for (int nt = 0; nt < 4; nt++)
            #pragma unroll
            for (int r = 0; r < 4; r++) acc[mt][nt][r] = 0.0f;

    auto issue = [&](int kt, int buf) {
        int kk = kt * GBK;
        #pragma unroll
        for (int i = 0; i < 2; i++) {
            int r = lr + i * 64;
            int gr = rowbase + r;
            if (gr >= NN) gr = NN - 1;   // clamp; garbage rows never stored
            cp16(&As[buf][r * SPAD + lc4], &A[gr * F_INN + kk + lc4]);
            cp16(&Bs[buf][r * SPAD + lc4], &Bsrc[r * F_INN + kk + lc4]);
        }
    };

    issue(0, 0);
    asm volatile("cp.async.commit_group;");

    for (int kt = 0; kt < KT; kt++) {
        int buf = kt & 1;
        if (kt + 1 < KT) {
            issue(kt + 1, (kt + 1) & 1);
            asm volatile("cp.async.commit_group;");
            asm volatile("cp.async.wait_group 1;");
        } else {
            asm volatile("cp.async.wait_group 0;");
        }
        // convert own copied words in place (self-visible after wait)
        #pragma unroll
        for (int i = 0; i < 2; i++) {
            int r = lr + i * 64;
            #pragma unroll
            for (int j = 0; j < 4; j++) {
                float* pa = &As[buf][r * SPAD + lc4 + j];
                float* pb = &Bs[buf][r * SPAD + lc4 + j];
                *pa = __uint_as_float(f2tf32(*pa));
                *pb = __uint_as_float(f2tf32(*pb));
            }
        }
        __syncthreads();

        #pragma unroll
        for (int ks = 0; ks < 2; ks++) {
            const int kof = ks * 8 + tg;
            unsigned af[4][4];
            #pragma unroll
            for (int mt = 0; mt < 4; mt++) {
                int r0 = wm * 64 + mt * 16 + grp;
                af[mt][0] = __float_as_uint(As[buf][r0 * SPAD + kof]);
                af[mt][1] = __float_as_uint(As[buf][(r0 + 8) * SPAD + kof]);
                af[mt][2] = __float_as_uint(As[buf][r0 * SPAD + kof + 4]);
                af[mt][3] = __float_as_uint(As[buf][(r0 + 8) * SPAD + kof + 4]);
            }
            unsigned bf[4][2];
            #pragma unroll
            for (int nt = 0; nt < 4; nt++) {
                int c0 = wn * 32 + nt * 8 + grp;
                bf[nt][0] = __float_as_uint(Bs[buf][c0 * SPAD + kof]);
                bf[nt][1] = __float_as_uint(Bs[buf][c0 * SPAD + kof + 4]);
            }
            #pragma unroll
            for (int mt = 0; mt < 4; mt++)
                #pragma unroll
                for (int nt = 0; nt < 4; nt++)
                    mma_tf32(acc[mt][nt][0], acc[mt][nt][1], acc[mt][nt][2], acc[mt][nt][3],
                             af[mt][0], af[mt][1], af[mt][2], af[mt][3],
                             bf[nt][0], bf[nt][1]);
        }
        __syncthreads();
    }

    #pragma unroll
    for (int mt = 0; mt < 4; mt++) {
        int row0 = rowbase + wm * 64 + mt * 16 + grp;
        int row1 = row0 + 8;
        #pragma unroll
        for (int nt = 0; nt < 4; nt++) {
            int col = ccol0 + wn * 32 + nt * 8 + 2 * tg;
            if (isfeat) {
                if (row0 < NN)
                    g_featb[row0 * 128 + (col >> 1)] =
                        __floats2bfloat162_rn(acc[mt][nt][0], acc[mt][nt][1]);
                if (row1 < NN)
                    g_featb[row1 * 128 + (col >> 1)] =
                        __floats2bfloat162_rn(acc[mt][nt][2], acc[mt][nt][3]);
            } else {
                if (row0 < NN)
                    *(float2*)&g_res[row0 * HD + col] = make_float2(acc[mt][nt][0], acc[mt][nt][1]);
                if (row1 < NN)
                    *(float2*)&g_res[row1 * HD + col] = make_float2(acc[mt][nt][2], acc[mt][nt][3]);
            }
        }
    }
}

// ---------------- K2b: per-node attention dots el, er (bf16 feat) ------------
__global__ void k_attn_nodes(const float* __restrict__ attn_l,
                             const float* __restrict__ attn_r) {
    int w = (blockIdx.x * blockDim.x + threadIdx.x) >> 5;
    int lane = threadIdx.x & 31;
    if (w >= NN) return;
    int h = lane >> 3, sub = lane & 7;
    uint4 v = *(const uint4*)&g_featb[w * 128 + lane * 4];   // dims lane*8 .. +7
    float2 f0 = __bfloat1622float2(*(__nv_bfloat162*)&v.x);
    float2 f1 = __bfloat1622float2(*(__nv_bfloat162*)&v.y);
    float2 f2 = __bfloat1622float2(*(__nv_bfloat162*)&v.z);
    float2 f3 = __bfloat1622float2(*(__nv_bfloat162*)&v.w);
    const float4* al = (const float4*)&attn_l[h * 64 + sub * 8];
    const float4* ar = (const float4*)&attn_r[h * 64 + sub * 8];
    float4 l0 = al[0], l1 = al[1];
    float4 r0 = ar[0], r1 = ar[1];
    float sl = f0.x*l0.x + f0.y*l0.y + f1.x*l0.z + f1.y*l0.w
             + f2.x*l1.x + f2.y*l1.y + f3.x*l1.z + f3.y*l1.w;
    float sr = f0.x*r0.x + f0.y*r0.y + f1.x*r0.z + f1.y*r0.w
             + f2.x*r1.x + f2.y*r1.y + f3.x*r1.z + f3.y*r1.w;
    #pragma unroll
    for (int off = 4; off; off >>= 1) {
        sl += __shfl_down_sync(0xffffffffu, sl, off, 8);
        sr += __shfl_down_sync(0xffffffffu, sr, off, 8);
    }
    if (sub == 0) { g_el[w * 4 + h] = sl; g_er[w * 4 + h] = sr; }
}

// ---------------- K3: edge logits + degree count ----------------
__global__ void k_edge1(const float* __restrict__ ef,
                        const int* __restrict__ src,
                        const int* __restrict__ dst) {
    __shared__ float Vs[F_EDGE * NH];
    if (threadIdx.x < 256) Vs[threadIdx.x] = g_V[threadIdx.x];
    __syncthreads();
    int t = blockIdx.x * blockDim.x + threadIdx.x;
    int e = t >> 3, sub = t & 7;
    if (e >= EE) return;
    const float4* p = (const float4*)&ef[e * 64 + sub * 8];
    float4 x0 = p[0], x1 = p[1];
    float xs[8] = {x0.x, x0.y, x0.z, x0.w, x1.x, x1.y, x1.z, x1.w};
    float a0 = 0.f, a1 = 0.f, a2 = 0.f, a3 = 0.f;
    #pragma unroll
    for (int j = 0; j < 8; j++) {
        float4 v = *(const float4*)&Vs[(sub * 8 + j) * 4];
        a0 += xs[j] * v.x; a1 += xs[j] * v.y; a2 += xs[j] * v.z; a3 += xs[j] * v.w;
    }
    #pragma unroll
    for (int off = 4; off; off >>= 1) {
        a0 += __shfl_xor_sync(0xffffffffu, a0, off);
        a1 += __shfl_xor_sync(0xffffffffu, a1, off);
        a2 += __shfl_xor_sync(0xffffffffu, a2, off);
        a3 += __shfl_xor_sync(0xffffffffu, a3, off);
    }
    int s = src[e], dd = dst[e];
    if (sub < 4) {
        int h = sub;
        float ee = (h == 0) ? a0 : (h == 1) ? a1 : (h == 2) ? a2 : a3;
        float v = g_el[s * 4 + h] + g_er[dd * 4 + h] + ee;
        v = (v > 0.0f) ? v : NEG_SLOPE * v;
        g_e[e * 4 + h] = v;
    }
    if (sub == 7) atomicAdd(&g_cnt[dd], 1);
}

// ---------------- scan: exclusive prefix sum of g_cnt -> g_off ----------------
__global__ void k_scanA() {
    __shared__ int sh[256];
    int b = blockIdx.x, t = threadIdx.x;
    int i = b * 256 + t;
    int v = (i < NN) ? g_cnt[i] : 0;
    sh[t] = v;
    __syncthreads();
    #pragma unroll
    for (int s = 128; s > 0; s >>= 1) {
        if (t < s) sh[t] += sh[t + s];
        __syncthreads();
    }
    if (t == 0) g_bsum[b] = sh[0];
}

__global__ void k_scanB() {
    __shared__ int sh[256];
    int t = threadIdx.x;
    int v = (t < NBLK) ? g_bsum[t] : 0;
    sh[t] = v;
    __syncthreads();
    #pragma unroll
    for (int s = 1; s < 256; s <<= 1) {
        int x = (t >= s) ? sh[t - s] : 0;
        __syncthreads();
        sh[t] += x;
        __syncthreads();
    }
    if (t < NBLK) g_bpre[t] = sh[t] - v;   // exclusive
}

__global__ void k_scanC() {
    __shared__ int sh[256];
    int b = blockIdx.x, t = threadIdx.x;
    int i = b * 256 + t;
    int v = (i < NN) ? g_cnt[i] : 0;
    sh[t] = v;
    __syncthreads();
    #pragma unroll
    for (int s = 1; s < 256; s <<= 1) {
        int x = (t >= s) ? sh[t - s] : 0;
        __syncthreads();
        sh[t] += x;
        __syncthreads();
    }
    if (i < NN) g_off[i] = g_bpre[b] + sh[t] - v;
}

// ---------------- K4: scatter edge ids into CSR slots ----------------
__global__ void k_scatter(const int* __restrict__ dst) {
    int e = blockIdx.x * blockDim.x + threadIdx.x;
    if (e >= EE) return;
    int dd = dst[e];
    int p = g_off[dd] + atomicAdd(&g_cur[dd], 1);
    g_eidx[p] = e;
}

// ---------------- K5: warp-per-node gather-reduce + norms + residual ----------
#define WPB 8
__global__ __launch_bounds__(256) void k_agg(const int* __restrict__ src,
                                             float* __restrict__ out) {
    __shared__ int   ssrc[WPB][32];
    __shared__ float sex[WPB][32 * 4];
    int wid = threadIdx.x >> 5, lane = threadIdx.x & 31;
    int n = blockIdx.x * WPB + wid;
    if (n >= NN) return;
    int beg = g_off[n];
    int deg = g_cnt[n];
    int h = lane >> 3;

    float acc[8];
    #pragma unroll
    for (int r = 0; r < 8; r++) acc[r] = 0.0f;
    float sum_ex = 0.0f;

    for (int base = 0; base < deg; base += 32) {
        int chunk = min(32, deg - base);
        if (lane < chunk) {
            int ei = g_eidx[beg + base + lane];
            ssrc[wid][lane] = src[ei];
            float4 lg = *(const float4*)&g_e[ei * 4];
            *(float4*)&sex[wid][lane * 4] = make_float4(__expf(lg.x), __expf(lg.y),
                                                        __expf(lg.z), __expf(lg.w));
        }
        __syncwarp();
        #pragma unroll 4
        for (int i = 0; i < chunk; i++) {
            float ex = sex[wid][i * 4 + h];
            int s = ssrc[wid][i];
            uint4 v = *(const uint4*)&g_featb[s * 128 + lane * 4];
            float2 f0 = __bfloat1622float2(*(__nv_bfloat162*)&v.x);
            float2 f1 = __bfloat1622float2(*(__nv_bfloat162*)&v.y);
            float2 f2 = __bfloat1622float2(*(__nv_bfloat162*)&v.z);
            float2 f3 = __bfloat1622float2(*(__nv_bfloat162*)&v.w);
            acc[0] += ex * f0.x; acc[1] += ex * f0.y;
            acc[2] += ex * f1.x; acc[3] += ex * f1.y;
            acc[4] += ex * f2.x; acc[5] += ex * f2.y;
            acc[6] += ex * f3.x; acc[7] += ex * f3.y;
            sum_ex += ex;
        }
        __syncwarp();
    }
    float invd = 1.0f / fmaxf((float)deg, 1.0f);
    float inv_ex = (sum_ex > 0.0f) ? (1.0f / sum_ex) : 0.0f;
    float sc = inv_ex * invd;
    const float4* rs = (const float4*)&g_res[n * HD + lane * 8];
    float4 r0 = rs[0], r1 = rs[1];
    float4 o0 = make_float4(acc[0]*sc + r0.x, acc[1]*sc + r0.y,
                            acc[2]*sc + r0.z, acc[3]*sc + r0.w);
    float4 o1 = make_float4(acc[4]*sc + r1.x, acc[5]*sc + r1.y,
                            acc[6]*sc + r1.z, acc[7]*sc + r1.w);
    float4* op = (float4*)&out[n * HD + lane * 8];
    op[0] = o0; op[1] = o1;
}

// ---------------- launch ----------------
extern "C" void kernel_launch(void* const* d_in, const int* in_sizes, int n_in,
                              void* d_out, int out_size) {
    const float* h_in    = (const float*)d_in[0];
    const float* ef      = (const float*)d_in[1];
    const int*   src     = (const int*)d_in[2];
    const int*   dst     = (const int*)d_in[3];
    const float* W_fc    = (const float*)d_in[4];
    const float* W_edge  = (const float*)d_in[5];
    const float* W_res   = (const float*)d_in[6];
    const float* attn_l  = (const float*)d_in[7];
    const float* attn_r  = (const float*)d_in[8];
    const float* attn_e  = (const float*)d_in[9];
    float* out = (float*)d_out;

    k_init<<<(NN + 255) / 256, 256>>>();
    k_prep<<<1, 256>>>(W_edge, attn_e);

    dim3 ggrid(4, (NN + GBM - 1) / GBM);   // 4 x 391
    k_gemm_tc<<<ggrid, 256>>>(h_in, W_fc, W_res);

    k_attn_nodes<<<(NN + 7) / 8, 256>>>(attn_l, attn_r);

    k_edge1<<<(EE * 8 + 255) / 256, 256>>>(ef, src, dst);

    k_scanA<<<NBLK, 256>>>();
    k_scanB<<<1, 256>>>();
    k_scanC<<<NBLK, 256>>>();

    k_scatter<<<(EE + 255) / 256, 256>>>(dst);

    k_agg<<<(NN + WPB - 1) / WPB, 256>>>(src, out);
}

// round 9
// speedup vs baseline: 1.1297x; 1.1297x over previous
#include <cuda_runtime.h>
#include <cuda_bf16.h>

#define NN 50000
#define EE 800000
#define F_INN 256
#define F_EDGE 64
#define NH 4
#define ND 64
#define HD 256
#define NEG_SLOPE 0.2f
#define NBLK 196   // ceil(NN/256)

// ---------------- scratch (static device globals; no allocation) ----------------
__device__ __nv_bfloat162 g_featb[NN * 128]; // h @ W_fc^T in bf16 pairs
__device__ float g_res[NN * HD];             // h @ W_res^T
__device__ float g_el[NN * NH];
__device__ float g_er[NN * NH];
__device__ float g_V[F_EDGE * NH];           // collapsed W_edge x attn_e, layout [j][h]
__device__ int   g_cnt[NN];                  // in-degree
__device__ int   g_off[NN];                  // CSR offsets (exclusive scan of cnt)
__device__ int   g_cur[NN];                  // scatter cursors
__device__ int   g_bsum[256];                // block sums for scan
__device__ int   g_bpre[256];                // block prefix
__device__ int   g_esrc[EE];                 // CSR: src node per slot
__device__ float g_eex[EE * NH];             // CSR: exp(e) per slot, 4 heads

// ---------------- helpers ----------------
__device__ __forceinline__ unsigned f2tf32(float f) {
    unsigned u;
    asm("cvt.rna.tf32.f32 %0, %1;" : "=r"(u) : "f"(f));
    return u;
}

__device__ __forceinline__ void mma_tf32(float& c0, float& c1, float& c2, float& c3,
                                         unsigned a0, unsigned a1, unsigned a2, unsigned a3,
                                         unsigned b0, unsigned b1) {
    asm volatile("mma.sync.aligned.m16n8k8.row.col.f32.tf32.tf32.f32 "
                 "{%0,%1,%2,%3}, {%4,%5,%6,%7}, {%8,%9}, {%0,%1,%2,%3};"
                 : "+f"(c0), "+f"(c1), "+f"(c2), "+f"(c3)
                 : "r"(a0), "r"(a1), "r"(a2), "r"(a3), "r"(b0), "r"(b1));
}

__device__ __forceinline__ void cp16(float* smem, const float* gmem) {
    unsigned s = (unsigned)__cvta_generic_to_shared(smem);
    asm volatile("cp.async.cg.shared.global [%0], [%1], 16;" :: "r"(s), "l"(gmem));
}

// ---------------- K0: init scratch ----------------
__global__ void k_init() {
    int i = blockIdx.x * blockDim.x + threadIdx.x;
    if (i < NN) { g_cnt[i] = 0; g_cur[i] = 0; }
}

// ---------------- K1: collapse W_edge with attn_e -> V [64,4] ----------------
__global__ void k_prep(const float* __restrict__ W_edge, const float* __restrict__ attn_e) {
    int tid = threadIdx.x;             // 256 threads
    int j = tid & 63, h = tid >> 6;
    float s = 0.0f;
    #pragma unroll 8
    for (int d = 0; d < 64; d++)
        s += W_edge[(h * 64 + d) * 64 + j] * attn_e[h * 64 + d];
    g_V[j * 4 + h] = s;
}

// ---------------- K1b: degree count (reads dst only) ----------------
__global__ void k_cnt(const int* __restrict__ dst) {
    int e = blockIdx.x * blockDim.x + threadIdx.x;
    if (e < EE) atomicAdd(&g_cnt[dst[e]], 1);
}

// ---------------- K2: tf32 GEMM, cp.async 2-stage, cvt at frag load ----------
#define GBM 128
#define GBN 128
#define GBK 16
#define KT  (F_INN / GBK)   // 16
#define SPAD 20             // words per row; conflict-free frag loads

__global__ __launch_bounds__(256) void k_gemm_tc(const float* __restrict__ A,
                                                 const float* __restrict__ Wfc,
                                                 const float* __restrict__ Wres) {
    __shared__ float As[2][GBM * SPAD];
    __shared__ float Bs[2][GBN * SPAD];

    const int colbase = blockIdx.x * GBN;    // 0,128,256,384
    const int rowbase = blockIdx.y * GBM;
    const bool isfeat = (colbase < 256);
    const float* Bsrc = isfeat ? (Wfc + colbase * F_INN)
                               : (Wres + (colbase - 256) * F_INN);
    const int ccol0 = isfeat ? colbase : colbase - 256;

    const int tid  = threadIdx.x;
    const int w    = tid >> 5;
    const int lane = tid & 31;
    const int grp  = lane >> 2;     // 0..7
    const int tg   = lane & 3;      // 0..3
    const int wm   = w & 1;
    const int wn   = w >> 1;

    const int lr  = tid >> 2;          // 0..63 (+64 on second pass)
    const int lc4 = (tid & 3) * 4;     // 0,4,8,12

    float acc[4][4][4];
    #pragma unroll
    for (int mt = 0; mt < 4; mt++)
        #pragma unroll
        for (int nt = 0; nt < 4; nt++)
            #pragma unroll
            for (int r = 0; r < 4; r++) acc[mt][nt][r] = 0.0f;

    auto issue = [&](int kt, int buf) {
        int kk = kt * GBK;
        #pragma unroll
        for (int i = 0; i < 2; i++) {
            int r = lr + i * 64;
            int gr = rowbase + r;
            if (gr >= NN) gr = NN - 1;   // clamp; garbage rows never stored
            cp16(&As[buf][r * SPAD + lc4], &A[gr * F_INN + kk + lc4]);
            cp16(&Bs[buf][r * SPAD + lc4], &Bsrc[r * F_INN + kk + lc4]);
        }
    };

    issue(0, 0);
    asm volatile("cp.async.commit_group;");

    for (int kt = 0; kt < KT; kt++) {
        int buf = kt & 1;
        if (kt + 1 < KT) {
            issue(kt + 1, (kt + 1) & 1);
            asm volatile("cp.async.commit_group;");
            asm volatile("cp.async.wait_group 1;");
        } else {
            asm volatile("cp.async.wait_group 0;");
        }
        __syncthreads();

        #pragma unroll
        for (int ks = 0; ks < 2; ks++) {
            const int kof = ks * 8 + tg;
            unsigned af[4][4];
            #pragma unroll
            for (int mt = 0; mt < 4; mt++) {
                int r0 = wm * 64 + mt * 16 + grp;
                af[mt][0] = f2tf32(As[buf][r0 * SPAD + kof]);
                af[mt][1] = f2tf32(As[buf][(r0 + 8) * SPAD + kof]);
                af[mt][2] = f2tf32(As[buf][r0 * SPAD + kof + 4]);
                af[mt][3] = f2tf32(As[buf][(r0 + 8) * SPAD + kof + 4]);
            }
            unsigned bf[4][2];
            #pragma unroll
            for (int nt = 0; nt < 4; nt++) {
                int c0 = wn * 32 + nt * 8 + grp;
                bf[nt][0] = f2tf32(Bs[buf][c0 * SPAD + kof]);
                bf[nt][1] = f2tf32(Bs[buf][c0 * SPAD + kof + 4]);
            }
            #pragma unroll
            for (int mt = 0; mt < 4; mt++)
                #pragma unroll
                for (int nt = 0; nt < 4; nt++)
                    mma_tf32(acc[mt][nt][0], acc[mt][nt][1], acc[mt][nt][2], acc[mt][nt][3],
                             af[mt][0], af[mt][1], af[mt][2], af[mt][3],
                             bf[nt][0], bf[nt][1]);
        }
        __syncthreads();
    }

    #pragma unroll
    for (int mt = 0; mt < 4; mt++) {
        int row0 = rowbase + wm * 64 + mt * 16 + grp;
        int row1 = row0 + 8;
        #pragma unroll
        for (int nt = 0; nt < 4; nt++) {
            int col = ccol0 + wn * 32 + nt * 8 + 2 * tg;
            if (isfeat) {
                if (row0 < NN)
                    g_featb[row0 * 128 + (col >> 1)] =
                        __floats2bfloat162_rn(acc[mt][nt][0], acc[mt][nt][1]);
                if (row1 < NN)
                    g_featb[row1 * 128 + (col >> 1)] =
                        __floats2bfloat162_rn(acc[mt][nt][2], acc[mt][nt][3]);
            } else {
                if (row0 < NN)
                    *(float2*)&g_res[row0 * HD + col] = make_float2(acc[mt][nt][0], acc[mt][nt][1]);
                if (row1 < NN)
                    *(float2*)&g_res[row1 * HD + col] = make_float2(acc[mt][nt][2], acc[mt][nt][3]);
            }
        }
    }
}

// ---------------- K2b: per-node attention dots el, er (bf16 feat) ------------
__global__ void k_attn_nodes(const float* __restrict__ attn_l,
                             const float* __restrict__ attn_r) {
    int w = (blockIdx.x * blockDim.x + threadIdx.x) >> 5;
    int lane = threadIdx.x & 31;
    if (w >= NN) return;
    int h = lane >> 3, sub = lane & 7;
    uint4 v = *(const uint4*)&g_featb[w * 128 + lane * 4];   // dims lane*8 .. +7
    float2 f0 = __bfloat1622float2(*(__nv_bfloat162*)&v.x);
    float2 f1 = __bfloat1622float2(*(__nv_bfloat162*)&v.y);
    float2 f2 = __bfloat1622float2(*(__nv_bfloat162*)&v.z);
    float2 f3 = __bfloat1622float2(*(__nv_bfloat162*)&v.w);
    const float4* al = (const float4*)&attn_l[h * 64 + sub * 8];
    const float4* ar = (const float4*)&attn_r[h * 64 + sub * 8];
    float4 l0 = al[0], l1 = al[1];
    float4 r0 = ar[0], r1 = ar[1];
    float sl = f0.x*l0.x + f0.y*l0.y + f1.x*l0.z + f1.y*l0.w
             + f2.x*l1.x + f2.y*l1.y + f3.x*l1.z + f3.y*l1.w;
    float sr = f0.x*r0.x + f0.y*r0.y + f1.x*r0.z + f1.y*r0.w
             + f2.x*r1.x + f2.y*r1.y + f3.x*r1.z + f3.y*r1.w;
    #pragma unroll
    for (int off = 4; off; off >>= 1) {
        sl += __shfl_down_sync(0xffffffffu, sl, off, 8);
        sr += __shfl_down_sync(0xffffffffu, sr, off, 8);
    }
    if (sub == 0) { g_el[w * 4 + h] = sl; g_er[w * 4 + h] = sr; }
}

// ---------------- scan: exclusive prefix sum of g_cnt -> g_off ----------------
__global__ void k_scanA() {
    __shared__ int sh[256];
    int b = blockIdx.x, t = threadIdx.x;
    int i = b * 256 + t;
    int v = (i < NN) ? g_cnt[i] : 0;
    sh[t] = v;
    __syncthreads();
    #pragma unroll
    for (int s = 128; s > 0; s >>= 1) {
        if (t < s) sh[t] += sh[t + s];
        __syncthreads();
    }
    if (t == 0) g_bsum[b] = sh[0];
}

__global__ void k_scanB() {
    __shared__ int sh[256];
    int t = threadIdx.x;
    int v = (t < NBLK) ? g_bsum[t] : 0;
    sh[t] = v;
    __syncthreads();
    #pragma unroll
    for (int s = 1; s < 256; s <<= 1) {
        int x = (t >= s) ? sh[t - s] : 0;
        __syncthreads();
        sh[t] += x;
        __syncthreads();
    }
    if (t < NBLK) g_bpre[t] = sh[t] - v;   // exclusive
}

__global__ void k_scanC() {
    __shared__ int sh[256];
    int b = blockIdx.x, t = threadIdx.x;
    int i = b * 256 + t;
    int v = (i < NN) ? g_cnt[i] : 0;
    sh[t] = v;
    __syncthreads();
    #pragma unroll
    for (int s = 1; s < 256; s <<= 1) {
        int x = (t >= s) ? sh[t - s] : 0;
        __syncthreads();
        sh[t] += x;
        __syncthreads();
    }
    if (i < NN) g_off[i] = g_bpre[b] + sh[t] - v;
}

// ---------------- K3: edge logits + fused CSR scatter ----------------
__global__ void k_edge1(const float* __restrict__ ef,
                        const int* __restrict__ src,
                        const int* __restrict__ dst) {
    __shared__ float Vs[F_EDGE * NH];
    if (threadIdx.x < 256) Vs[threadIdx.x] = g_V[threadIdx.x];
    __syncthreads();
    int t = blockIdx.x * blockDim.x + threadIdx.x;
    int e = t >> 3, sub = t & 7;
    int lane = threadIdx.x & 31;
    if (e >= EE) return;
    const float4* p4 = (const float4*)&ef[e * 64 + sub * 8];
    float4 x0 = p4[0], x1 = p4[1];
    float xs[8] = {x0.x, x0.y, x0.z, x0.w, x1.x, x1.y, x1.z, x1.w};
    float a0 = 0.f, a1 = 0.f, a2 = 0.f, a3 = 0.f;
    #pragma unroll
    for (int j = 0; j < 8; j++) {
        float4 v = *(const float4*)&Vs[(sub * 8 + j) * 4];
        a0 += xs[j] * v.x; a1 += xs[j] * v.y; a2 += xs[j] * v.z; a3 += xs[j] * v.w;
    }
    #pragma unroll
    for (int off = 4; off; off >>= 1) {
        a0 += __shfl_xor_sync(0xffffffffu, a0, off);
        a1 += __shfl_xor_sync(0xffffffffu, a1, off);
        a2 += __shfl_xor_sync(0xffffffffu, a2, off);
        a3 += __shfl_xor_sync(0xffffffffu, a3, off);
    }
    int s = src[e], dd = dst[e];
    // claim CSR slot (one lane per edge-group), broadcast to the 8-lane group
    int p = 0;
    if (sub == 0) p = g_off[dd] + atomicAdd(&g_cur[dd], 1);
    p = __shfl_sync(0xffffffffu, p, lane & ~7);
    if (sub == 0) g_esrc[p] = s;
    if (sub < 4) {
        int h = sub;
        float ee = (h == 0) ? a0 : (h == 1) ? a1 : (h == 2) ? a2 : a3;
        float v = g_el[s * 4 + h] + g_er[dd * 4 + h] + ee;
        v = (v > 0.0f) ? v : NEG_SLOPE * v;
        g_eex[p * 4 + h] = __expf(v);
    }
}

// ---------------- K5: per-node gather-reduce (bf16 rows) + norms + residual ----
#define AGG_CHUNK 64
__global__ __launch_bounds__(128) void k_agg(float* __restrict__ out) {
    __shared__ int   ssrc[AGG_CHUNK];
    __shared__ float sex[AGG_CHUNK * 4];
    int n = blockIdx.x;
    int tid = threadIdx.x;            // 0..127, owns dims (2*tid, 2*tid+1)
    int h = tid >> 5;
    int beg = g_off[n];
    int deg = g_cnt[n];

    float accx = 0.0f, accy = 0.0f, sum_ex = 0.0f;
    for (int base = 0; base < deg; base += AGG_CHUNK) {
        int chunk = min(AGG_CHUNK, deg - base);
        if (tid < chunk) ssrc[tid] = g_esrc[beg + base + tid];
        for (int i = tid; i < chunk * 4; i += 128)
            sex[i] = g_eex[(beg + base) * 4 + i];
        __syncthreads();
        #pragma unroll 4
        for (int i = 0; i < chunk; i++) {
            float ex = sex[i * 4 + h];
            __nv_bfloat162 v = g_featb[ssrc[i] * 128 + tid];
            float2 f = __bfloat1622float2(v);
            accx += ex * f.x;
            accy += ex * f.y;
            sum_ex += ex;
        }
        __syncthreads();
    }
    float invd = 1.0f / fmaxf((float)deg, 1.0f);
    float inv_ex = (sum_ex > 0.0f) ? (1.0f / sum_ex) : 0.0f;
    float sc = inv_ex * invd;
    float2 rs = *(const float2*)&g_res[n * HD + tid * 2];
    *(float2*)&out[n * HD + tid * 2] = make_float2(accx * sc + rs.x, accy * sc + rs.y);
}

// ---------------- launch ----------------
extern "C" void kernel_launch(void* const* d_in, const int* in_sizes, int n_in,
                              void* d_out, int out_size) {
    const float* h_in    = (const float*)d_in[0];
    const float* ef      = (const float*)d_in[1];
    const int*   src     = (const int*)d_in[2];
    const int*   dst     = (const int*)d_in[3];
    const float* W_fc    = (const float*)d_in[4];
    const float* W_edge  = (const float*)d_in[5];
    const float* W_res   = (const float*)d_in[6];
    const float* attn_l  = (const float*)d_in[7];
    const float* attn_r  = (const float*)d_in[8];
    const float* attn_e  = (const float*)d_in[9];
    float* out = (float*)d_out;

    k_init<<<(NN + 255) / 256, 256>>>();
    k_prep<<<1, 256>>>(W_edge, attn_e);
    k_cnt<<<(EE + 255) / 256, 256>>>(dst);

    k_scanA<<<NBLK, 256>>>();
    k_scanB<<<1, 256>>>();
    k_scanC<<<NBLK, 256>>>();

    dim3 ggrid(4, (NN + GBM - 1) / GBM);   // 4 x 391
    k_gemm_tc<<<ggrid, 256>>>(h_in, W_fc, W_res);

    k_attn_nodes<<<(NN + 7) / 8, 256>>>(attn_l, attn_r);

    k_edge1<<<(EE * 8 + 255) / 256, 256>>>(ef, src, dst);

    k_agg<<<NN, 128>>>(out);
}